// round 9
// baseline (speedup 1.0000x reference)
#include <cuda_runtime.h>
#include <cstdint>

#define D      512
#define BATCH  256
#define TOPK   2
#define NEXP   16
#define NPAIR  (BATCH * TOPK)
#define NQ     4           // batch quarters
#define QPAIR  (NPAIR / NQ)   // 128 pairs per quarter
#define QB     (BATCH / NQ)   // 64 batches per quarter
#define MAXCHQ 24          // worst-case sum ceil(M_{e,q}/16) = 8 + 15 = 23
#define XS_STRIDE 20       // 16 data + 4 pad floats; 80B rows, 16B-aligned

// ---------------- scratch ----------------
__device__ float g_iv[NPAIR * D];
__device__ float g_ov[NPAIR * D];
__device__ float g_dv[NPAIR * D];
__device__ float g_bv[NPAIR * D];
__device__ int   g_list_w[NPAIR];          // grouped by quarter [q*128, q*128+128)
__device__ int   g_list_b[NPAIR];
__device__ int   g_chunks_w[NQ * MAXCHQ];  // packed: start | e<<16 | rows<<24
__device__ int   g_chunks_b[NQ * MAXCHQ];
__device__ int   g_nch_w[NQ], g_nch_b[NQ];

// ---------------- PDL device helpers ----------------
__device__ __forceinline__ void pdl_trigger() {
    asm volatile("griddepcontrol.launch_dependents;" ::: "memory");
}

// ---------------- kernel 0: per-quarter counting sort + chunk lists ----------------
__global__ void sort_kernel(const int* __restrict__ widx, const int* __restrict__ bidx) {
    __shared__ int cw[NQ][NEXP], cb[NQ][NEXP];
    __shared__ int offw[NQ][NEXP + 1], offb[NQ][NEXP + 1];
    __shared__ int pw[NQ][NEXP], pb[NQ][NEXP];
    int t = threadIdx.x;                       // 512 threads == global pair id
    int q = t >> 7;                            // pair quarter
    if (t < NQ * NEXP) { cw[t >> 4][t & 15] = 0; cb[t >> 4][t & 15] = 0; }
    __syncthreads();
    int ew = widx[t];
    int eb = bidx[t];
    atomicAdd(&cw[q][ew], 1);
    atomicAdd(&cb[q][eb], 1);
    __syncthreads();
    if (t < 2 * NQ) {                          // one thread per (quarter, type)
        int qq = t >> 1;
        bool isW = (t & 1) == 0;
        int* cnt  = isW ? cw[qq] : cb[qq];
        int* off  = isW ? offw[qq] : offb[qq];
        int* chk  = (isW ? g_chunks_w : g_chunks_b) + qq * MAXCHQ;
        int s = 0, n = 0;
        for (int e = 0; e < NEXP; e++) {
            off[e] = s;
            int c = cnt[e];
            for (int c0 = 0; c0 < c; c0 += 16) {
                int rows = min(16, c - c0);
                chk[n++] = (s + c0) | (e << 16) | (rows << 24);
            }
            s += c;
        }
        off[NEXP] = s;
        if (isW) g_nch_w[qq] = n; else g_nch_b[qq] = n;
    }
    __syncthreads();
    if (t < NQ * NEXP) {
        pw[t >> 4][t & 15] = offw[t >> 4][t & 15];
        pb[t >> 4][t & 15] = offb[t >> 4][t & 15];
    }
    __syncthreads();
    int posw = atomicAdd(&pw[q][ew], 1);
    g_list_w[q * QPAIR + posw] = t;
    int posb = atomicAdd(&pb[q][eb], 1);
    g_list_b[q * QPAIR + posb] = t;
}

// ---------------- packed f32x2 helpers ----------------
__device__ __forceinline__ uint64_t dupf2(float w) {
    uint64_t r;
    asm("mov.b64 %0, {%1, %1};" : "=l"(r) : "r"(__float_as_uint(w)));
    return r;
}
__device__ __forceinline__ void fma2(uint64_t& acc, uint64_t a, uint64_t b) {
    asm("fma.rn.f32x2 %0, %1, %2, %0;" : "+l"(acc) : "l"(a), "l"(b));
}

// ---------------- kernel 1: grouped GEMM for one quarter (r5-proven body) ----------
// grid = (4 col-tiles of 128, MAXCHQ chunks, 4 banks), block = 128 threads.
// Launched with PDL for q>=1: runs concurrently under the previous quarter's mix.
__global__ __launch_bounds__(128) void gemm_kernel(
    const float* __restrict__ x,
    const float* __restrict__ iw, const float* __restrict__ ow,
    const float* __restrict__ dw, const float* __restrict__ bb,
    int q) {

    int bank = blockIdx.z;
    bool isW = bank < 3;
    int nch = isW ? g_nch_w[q] : g_nch_b[q];
    if ((int)blockIdx.y >= nch) return;

    __shared__ __align__(16) float xs[D * XS_STRIDE];   // 40KB

    int packed = ((isW ? g_chunks_w : g_chunks_b) + q * MAXCHQ)[blockIdx.y];
    int s    = packed & 0xFFFF;           // local start within quarter
    int e    = (packed >> 16) & 0xFF;
    int rows = (packed >> 24) & 0xFF;

    const int* list = (isW ? g_list_w : g_list_b) + q * QPAIR;
    const float* W  = ((bank == 0) ? iw : (bank == 1) ? ow : (bank == 2) ? dw : bb)
                      + (size_t)e * D * D;
    float* out = (bank == 0) ? g_iv : (bank == 1) ? g_ov : (bank == 2) ? g_dv : g_bv;

    int t   = threadIdx.x;
    int col = blockIdx.x * 128 + t;

    for (int idx2 = t; idx2 < 16 * D; idx2 += 128) {
        int m  = idx2 >> 9;
        int kk = idx2 & (D - 1);
        float val = 0.0f;
        if (m < rows) val = x[(list[s + m] >> 1) * D + kk];
        xs[kk * XS_STRIDE + m] = val;
    }
    __syncthreads();

    uint64_t acc[8];
#pragma unroll
    for (int j = 0; j < 8; j++) acc[j] = 0ull;

    const float* Wc = W + col;
#pragma unroll 16
    for (int kk = 0; kk < D; kk++) {
        float w = Wc[kk * D];
        uint64_t ww = dupf2(w);
        const ulonglong2* row = (const ulonglong2*)&xs[kk * XS_STRIDE];
        ulonglong2 r0 = row[0];
        ulonglong2 r1 = row[1];
        ulonglong2 r2 = row[2];
        ulonglong2 r3 = row[3];
        fma2(acc[0], r0.x, ww);
        fma2(acc[1], r0.y, ww);
        fma2(acc[2], r1.x, ww);
        fma2(acc[3], r1.y, ww);
        fma2(acc[4], r2.x, ww);
        fma2(acc[5], r2.y, ww);
        fma2(acc[6], r3.x, ww);
        fma2(acc[7], r3.y, ww);
    }

#pragma unroll
    for (int j = 0; j < 8; j++) {
        float2 f2 = *reinterpret_cast<float2*>(&acc[j]);
        int r = 2 * j;
        if (r < rows)     out[(size_t)list[s + r] * D + col]     = f2.x;
        if (r + 1 < rows) out[(size_t)list[s + r + 1] * D + col] = f2.y;
    }
}

// ---------------- kernel 2: mix + analytic LN + bmix for one quarter -------------
// grid = (4 row-tiles of 128, QB batches), block = 128. Launched normally (starts
// only after its gemm completes). Fires PDL trigger at entry so the NEXT quarter's
// gemm launches and runs concurrently under this kernel's write stream.
__global__ __launch_bounds__(128) void mix_ln_kernel(
    const float* __restrict__ wp, const float* __restrict__ bp,
    float* __restrict__ outp, int q) {

    pdl_trigger();   // release next quarter's gemm immediately

    int b  = q * QB + blockIdx.y;
    int r0 = blockIdx.x * 128;
    int t  = threadIdx.x;

    __shared__ float u[D], v[D];
    __shared__ __align__(16) float4 sparams[128];   // {pr, qr, c, gr}
    __shared__ float red[4][5];

    const float* u_g = g_ov + (size_t)(2 * b) * D;
    const float* v_g = g_ov + (size_t)(2 * b + 1) * D;
    float4 u4 = ((const float4*)u_g)[t];
    float4 v4 = ((const float4*)v_g)[t];
    ((float4*)u)[t] = u4;
    ((float4*)v)[t] = v4;

    float lu  = u4.x + u4.y + u4.z + u4.w;
    float lv  = v4.x + v4.y + v4.z + v4.w;
    float luu = u4.x * u4.x + u4.y * u4.y + u4.z * u4.z + u4.w * u4.w;
    float lvv = v4.x * v4.x + v4.y * v4.y + v4.z * v4.z + v4.w * v4.w;
    float luv = u4.x * v4.x + u4.y * v4.y + u4.z * v4.z + u4.w * v4.w;
#pragma unroll
    for (int sft = 16; sft > 0; sft >>= 1) {
        lu  += __shfl_xor_sync(0xffffffffu, lu, sft);
        lv  += __shfl_xor_sync(0xffffffffu, lv, sft);
        luu += __shfl_xor_sync(0xffffffffu, luu, sft);
        lvv += __shfl_xor_sync(0xffffffffu, lvv, sft);
        luv += __shfl_xor_sync(0xffffffffu, luv, sft);
    }
    int lane = t & 31, wrp = t >> 5;
    if (lane == 0) {
        red[wrp][0] = lu; red[wrp][1] = lv; red[wrp][2] = luu;
        red[wrp][3] = lvv; red[wrp][4] = luv;
    }
    __syncthreads();
    float Su  = red[0][0] + red[1][0] + red[2][0] + red[3][0];
    float Sv  = red[0][1] + red[1][1] + red[2][1] + red[3][1];
    float Suu = red[0][2] + red[1][2] + red[2][2] + red[3][2];
    float Svv = red[0][3] + red[1][3] + red[2][3] + red[3][3];
    float Suv = red[0][4] + red[1][4] + red[2][4] + red[3][4];

    {
        int i = r0 + t;
        float wp0 = wp[2 * b], wp1 = wp[2 * b + 1];
        float p = wp0 * g_iv[(size_t)(2 * b) * D + i];
        float qq = wp1 * g_iv[(size_t)(2 * b + 1) * D + i];
        float g = wp0 * g_dv[(size_t)(2 * b) * D + i]
                + wp1 * g_dv[(size_t)(2 * b + 1) * D + i];
        const float invD = 1.0f / (float)D;
        float mean = (p * Su + qq * Sv + g) * invD;
        float ex2  = (p * p * Suu + 2.0f * p * qq * Suv + qq * qq * Svv
                      + 2.0f * g * (p * u[i] + qq * v[i]) + g * g) * invD;
        float var  = ex2 - mean * mean;
        float rstd = rsqrtf(var + 1e-5f);
        float4 pr;
        pr.x = p * rstd;
        pr.y = qq * rstd;
        pr.z = -mean * rstd;
        pr.w = g * rstd;
        sparams[t] = pr;
    }
    __syncthreads();

    float* orow = outp + ((size_t)b * D + r0) * D + (t << 2);

    if (wrp == blockIdx.x) {
        int base = t << 2;
#pragma unroll 4
        for (int r = 0; r < 128; r++) {
            float4 P = sparams[r];
            float4 o;
            o.x = fmaf(P.y, v4.x, fmaf(P.x, u4.x, P.z));
            o.y = fmaf(P.y, v4.y, fmaf(P.x, u4.y, P.z));
            o.z = fmaf(P.y, v4.z, fmaf(P.x, u4.z, P.z));
            o.w = fmaf(P.y, v4.w, fmaf(P.x, u4.w, P.z));
            int dj = (r0 + r) - base;
            if (dj == 0) o.x += P.w;
            if (dj == 1) o.y += P.w;
            if (dj == 2) o.z += P.w;
            if (dj == 3) o.w += P.w;
            *(float4*)(orow + (size_t)r * D) = o;
        }
    } else {
#pragma unroll 4
        for (int r = 0; r < 128; r++) {
            float4 P = sparams[r];
            float4 o;
            o.x = fmaf(P.y, v4.x, fmaf(P.x, u4.x, P.z));
            o.y = fmaf(P.y, v4.y, fmaf(P.x, u4.y, P.z));
            o.z = fmaf(P.y, v4.z, fmaf(P.x, u4.z, P.z));
            o.w = fmaf(P.y, v4.w, fmaf(P.x, u4.w, P.z));
            *(float4*)(orow + (size_t)r * D) = o;
        }
    }

    // bmix (row-tile 0 only): bmix[b,:] = bp0*bv0 + bp1*bv1
    if (blockIdx.x == 0) {
        float bp0 = bp[2 * b], bp1 = bp[2 * b + 1];
        float4 b0 = ((const float4*)(g_bv + (size_t)(2 * b) * D))[t];
        float4 b1 = ((const float4*)(g_bv + (size_t)(2 * b + 1) * D))[t];
        float4 o;
        o.x = bp0 * b0.x + bp1 * b1.x;
        o.y = bp0 * b0.y + bp1 * b1.y;
        o.z = bp0 * b0.z + bp1 * b1.z;
        o.w = bp0 * b0.w + bp1 * b1.w;
        ((float4*)(outp + (size_t)BATCH * D * D + (size_t)b * D))[t] = o;
    }
}

// ---------------- launch: quarter-pipelined with PDL ----------------
extern "C" void kernel_launch(void* const* d_in, const int* in_sizes, int n_in,
                              void* d_out, int out_size) {
    const float* x    = (const float*)d_in[0];
    const float* wp   = (const float*)d_in[1];
    const float* bpr  = (const float*)d_in[2];
    const float* iw   = (const float*)d_in[3];
    const float* ow   = (const float*)d_in[4];
    const float* dw   = (const float*)d_in[5];
    const float* bb   = (const float*)d_in[6];
    const int*   widx = (const int*)d_in[7];
    const int*   bidx = (const int*)d_in[8];
    float* outp = (float*)d_out;

    sort_kernel<<<1, NPAIR>>>(widx, bidx);

    for (int q = 0; q < NQ; q++) {
        if (q == 0) {
            gemm_kernel<<<dim3(4, MAXCHQ, 4), 128>>>(x, iw, ow, dw, bb, q);
        } else {
            // PDL launch: may start as soon as the previous mix fires its trigger.
            // gemm has no data dependence on any mix, so it runs (not waits).
            cudaLaunchConfig_t cfg = {};
            cfg.gridDim  = dim3(4, MAXCHQ, 4);
            cfg.blockDim = dim3(128, 1, 1);
            cfg.dynamicSmemBytes = 0;
            cfg.stream = 0;
            cudaLaunchAttribute attr[1];
            attr[0].id = cudaLaunchAttributeProgrammaticStreamSerialization;
            attr[0].val.programmaticStreamSerializationAllowed = 1;
            cfg.attrs = attr;
            cfg.numAttrs = 1;
            cudaLaunchKernelEx(&cfg, gemm_kernel, x, iw, ow, dw, bb, q);
        }
        // normal launch: starts only after gemm_q completes (no spinning blocks)
        mix_ln_kernel<<<dim3(4, QB), 128>>>(wp, bpr, outp, q);
    }
}

// round 10
// speedup vs baseline: 2.3908x; 2.3908x over previous
#include <cuda_runtime.h>
#include <cstdint>

#define D      512
#define BATCH  256
#define TOPK   2
#define NEXP   16
#define NPAIR  (BATCH * TOPK)
#define MAXCH  48          // worst-case sum ceil(M_e/16) over 16 experts
#define NKS    4           // k-splits
#define KSL    (D / NKS)   // 128 kk per split
#define XS_STRIDE 20       // 16 data + 4 pad floats; 80B rows, 16B-aligned

// ---------------- scratch (per-split partial buffers) ----------------
__device__ float g_iv[NKS * NPAIR * D];
__device__ float g_ov[NKS * NPAIR * D];
__device__ float g_dv[NKS * NPAIR * D];
__device__ float g_bv[NKS * NPAIR * D];
__device__ int   g_list_w[NPAIR];
__device__ int   g_list_b[NPAIR];
__device__ int   g_chunks_w[MAXCH];   // packed: start | e<<16 | rows<<24
__device__ int   g_chunks_b[MAXCH];
__device__ int   g_nch_w, g_nch_b;

// ---------------- kernel 0: counting sort + chunk work-list ----------------
__global__ void sort_kernel(const int* __restrict__ widx, const int* __restrict__ bidx) {
    __shared__ int cw[NEXP], cb[NEXP], offw[NEXP + 1], offb[NEXP + 1], pw[NEXP], pb[NEXP];
    int t = threadIdx.x;                       // 512 threads == pair id
    if (t < NEXP) { cw[t] = 0; cb[t] = 0; }
    __syncthreads();
    int ew = widx[t];
    int eb = bidx[t];
    atomicAdd(&cw[ew], 1);
    atomicAdd(&cb[eb], 1);
    __syncthreads();
    if (t == 0) {
        int s = 0;
        for (int e = 0; e < NEXP; e++) { offw[e] = s; s += cw[e]; }
        offw[NEXP] = s;
        int n = 0;
        for (int e = 0; e < NEXP; e++)
            for (int c = offw[e]; c < offw[e + 1]; c += 16) {
                int rows = min(16, offw[e + 1] - c);
                g_chunks_w[n++] = c | (e << 16) | (rows << 24);
            }
        g_nch_w = n;
    }
    if (t == 32) {
        int s = 0;
        for (int e = 0; e < NEXP; e++) { offb[e] = s; s += cb[e]; }
        offb[NEXP] = s;
        int n = 0;
        for (int e = 0; e < NEXP; e++)
            for (int c = offb[e]; c < offb[e + 1]; c += 16) {
                int rows = min(16, offb[e + 1] - c);
                g_chunks_b[n++] = c | (e << 16) | (rows << 24);
            }
        g_nch_b = n;
    }
    __syncthreads();
    if (t < NEXP) { pw[t] = offw[t]; pb[t] = offb[t]; }
    __syncthreads();
    int posw = atomicAdd(&pw[ew], 1);
    g_list_w[posw] = t;
    int posb = atomicAdd(&pb[eb], 1);
    g_list_b[posb] = t;
}

// ---------------- packed f32x2 helpers ----------------
__device__ __forceinline__ uint64_t dupf2(float w) {
    uint64_t r;
    asm("mov.b64 %0, {%1, %1};" : "=l"(r) : "r"(__float_as_uint(w)));
    return r;
}
__device__ __forceinline__ void fma2(uint64_t& acc, uint64_t a, uint64_t b) {
    asm("fma.rn.f32x2 %0, %1, %2, %0;" : "+l"(acc) : "l"(a), "l"(b));
}

// ---------------- kernel 1: split-K grouped GEMM (FFMA2) ----------------
// grid = (4 col-tiles of 128, MAXCH chunks, 4 banks * NKS ksplits), block = 128.
// Each block accumulates a partial dot over kk in [ks*128, ks*128+128) into its
// split's scratch buffer. smem 10KB => ~14 blocks/SM resident (2048 active blocks,
// ~55 warps/SM) — LDG latency fully covered. W/x read traffic unchanged vs full-K.
__global__ __launch_bounds__(128) void gemm_kernel(
    const float* __restrict__ x,
    const float* __restrict__ iw, const float* __restrict__ ow,
    const float* __restrict__ dw, const float* __restrict__ bb) {

    int z    = blockIdx.z;
    int bank = z & 3;
    int ks   = z >> 2;
    int koff = ks * KSL;
    bool isW = bank < 3;
    int nch = isW ? g_nch_w : g_nch_b;
    if ((int)blockIdx.y >= nch) return;

    __shared__ __align__(16) float xs[KSL * XS_STRIDE];   // 10KB

    int packed = (isW ? g_chunks_w : g_chunks_b)[blockIdx.y];
    int s    = packed & 0xFFFF;
    int e    = (packed >> 16) & 0xFF;
    int rows = (packed >> 24) & 0xFF;

    const int* list = isW ? g_list_w : g_list_b;
    const float* W  = ((bank == 0) ? iw : (bank == 1) ? ow : (bank == 2) ? dw : bb)
                      + (size_t)e * D * D;
    float* out = ((bank == 0) ? g_iv : (bank == 1) ? g_ov : (bank == 2) ? g_dv : g_bv)
                 + (size_t)ks * NPAIR * D;

    int t   = threadIdx.x;
    int col = blockIdx.x * 128 + t;

    // fill transposed x sub-chunk [16 rows x 128 kk] (coalesced LDG; zero-pad)
    for (int idx2 = t; idx2 < 16 * KSL; idx2 += 128) {
        int m  = idx2 >> 7;
        int kk = idx2 & (KSL - 1);
        float val = 0.0f;
        if (m < rows) val = x[(list[s + m] >> 1) * D + koff + kk];
        xs[kk * XS_STRIDE + m] = val;
    }
    __syncthreads();

    uint64_t acc[8];
#pragma unroll
    for (int j = 0; j < 8; j++) acc[j] = 0ull;

    const float* Wc = W + (size_t)koff * D + col;
#pragma unroll 16
    for (int kk = 0; kk < KSL; kk++) {
        float w = Wc[kk * D];
        uint64_t ww = dupf2(w);
        const ulonglong2* row = (const ulonglong2*)&xs[kk * XS_STRIDE];
        ulonglong2 r0 = row[0];
        ulonglong2 r1 = row[1];
        ulonglong2 r2 = row[2];
        ulonglong2 r3 = row[3];
        fma2(acc[0], r0.x, ww);
        fma2(acc[1], r0.y, ww);
        fma2(acc[2], r1.x, ww);
        fma2(acc[3], r1.y, ww);
        fma2(acc[4], r2.x, ww);
        fma2(acc[5], r2.y, ww);
        fma2(acc[6], r3.x, ww);
        fma2(acc[7], r3.y, ww);
    }

#pragma unroll
    for (int j = 0; j < 8; j++) {
        float2 f2 = *reinterpret_cast<float2*>(&acc[j]);
        int r = 2 * j;
        if (r < rows)     out[(size_t)list[s + r] * D + col]     = f2.x;
        if (r + 1 < rows) out[(size_t)list[s + r + 1] * D + col] = f2.y;
    }
}

// ---------------- kernel 2: sum k-splits + rank-2 mix + analytic LN + bmix --------
__global__ __launch_bounds__(128) void mix_ln_kernel(
    const float* __restrict__ wp, const float* __restrict__ bp,
    float* __restrict__ outp) {

    int b  = blockIdx.y;
    int r0 = blockIdx.x * 128;
    int t  = threadIdx.x;

    __shared__ float u[D], v[D];
    __shared__ __align__(16) float4 sparams[128];   // {pr, qr, c, gr}
    __shared__ float red[4][5];

    // u,v = sum of k-split partials of ov
    float4 u4 = make_float4(0.f, 0.f, 0.f, 0.f);
    float4 v4 = make_float4(0.f, 0.f, 0.f, 0.f);
#pragma unroll
    for (int ks = 0; ks < NKS; ks++) {
        const float* base = g_ov + (size_t)ks * NPAIR * D;
        float4 a = ((const float4*)(base + (size_t)(2 * b) * D))[t];
        float4 c = ((const float4*)(base + (size_t)(2 * b + 1) * D))[t];
        u4.x += a.x; u4.y += a.y; u4.z += a.z; u4.w += a.w;
        v4.x += c.x; v4.y += c.y; v4.z += c.z; v4.w += c.w;
    }
    ((float4*)u)[t] = u4;
    ((float4*)v)[t] = v4;

    float lu  = u4.x + u4.y + u4.z + u4.w;
    float lv  = v4.x + v4.y + v4.z + v4.w;
    float luu = u4.x * u4.x + u4.y * u4.y + u4.z * u4.z + u4.w * u4.w;
    float lvv = v4.x * v4.x + v4.y * v4.y + v4.z * v4.z + v4.w * v4.w;
    float luv = u4.x * v4.x + u4.y * v4.y + u4.z * v4.z + u4.w * v4.w;
#pragma unroll
    for (int sft = 16; sft > 0; sft >>= 1) {
        lu  += __shfl_xor_sync(0xffffffffu, lu, sft);
        lv  += __shfl_xor_sync(0xffffffffu, lv, sft);
        luu += __shfl_xor_sync(0xffffffffu, luu, sft);
        lvv += __shfl_xor_sync(0xffffffffu, lvv, sft);
        luv += __shfl_xor_sync(0xffffffffu, luv, sft);
    }
    int lane = t & 31, wrp = t >> 5;
    if (lane == 0) {
        red[wrp][0] = lu; red[wrp][1] = lv; red[wrp][2] = luu;
        red[wrp][3] = lvv; red[wrp][4] = luv;
    }
    __syncthreads();
    float Su  = red[0][0] + red[1][0] + red[2][0] + red[3][0];
    float Sv  = red[0][1] + red[1][1] + red[2][1] + red[3][1];
    float Suu = red[0][2] + red[1][2] + red[2][2] + red[3][2];
    float Svv = red[0][3] + red[1][3] + red[2][3] + red[3][3];
    float Suv = red[0][4] + red[1][4] + red[2][4] + red[3][4];

    {
        int i = r0 + t;
        float iv0 = 0.f, iv1 = 0.f, dv0 = 0.f, dv1 = 0.f;
#pragma unroll
        for (int ks = 0; ks < NKS; ks++) {
            size_t off = (size_t)ks * NPAIR * D;
            iv0 += g_iv[off + (size_t)(2 * b) * D + i];
            iv1 += g_iv[off + (size_t)(2 * b + 1) * D + i];
            dv0 += g_dv[off + (size_t)(2 * b) * D + i];
            dv1 += g_dv[off + (size_t)(2 * b + 1) * D + i];
        }
        float wp0 = wp[2 * b], wp1 = wp[2 * b + 1];
        float p = wp0 * iv0;
        float q = wp1 * iv1;
        float g = wp0 * dv0 + wp1 * dv1;
        const float invD = 1.0f / (float)D;
        float mean = (p * Su + q * Sv + g) * invD;
        float ex2  = (p * p * Suu + 2.0f * p * q * Suv + q * q * Svv
                      + 2.0f * g * (p * u[i] + q * v[i]) + g * g) * invD;
        float var  = ex2 - mean * mean;
        float rstd = rsqrtf(var + 1e-5f);
        float4 pr;
        pr.x = p * rstd;
        pr.y = q * rstd;
        pr.z = -mean * rstd;
        pr.w = g * rstd;
        sparams[t] = pr;
    }
    __syncthreads();

    float* orow = outp + ((size_t)b * D + r0) * D + (t << 2);

    if (wrp == blockIdx.x) {
        int base = t << 2;
#pragma unroll 4
        for (int r = 0; r < 128; r++) {
            float4 P = sparams[r];
            float4 o;
            o.x = fmaf(P.y, v4.x, fmaf(P.x, u4.x, P.z));
            o.y = fmaf(P.y, v4.y, fmaf(P.x, u4.y, P.z));
            o.z = fmaf(P.y, v4.z, fmaf(P.x, u4.z, P.z));
            o.w = fmaf(P.y, v4.w, fmaf(P.x, u4.w, P.z));
            int dj = (r0 + r) - base;
            if (dj == 0) o.x += P.w;
            if (dj == 1) o.y += P.w;
            if (dj == 2) o.z += P.w;
            if (dj == 3) o.w += P.w;
            *(float4*)(orow + (size_t)r * D) = o;
        }
    } else {
#pragma unroll 4
        for (int r = 0; r < 128; r++) {
            float4 P = sparams[r];
            float4 o;
            o.x = fmaf(P.y, v4.x, fmaf(P.x, u4.x, P.z));
            o.y = fmaf(P.y, v4.y, fmaf(P.x, u4.y, P.z));
            o.z = fmaf(P.y, v4.z, fmaf(P.x, u4.z, P.z));
            o.w = fmaf(P.y, v4.w, fmaf(P.x, u4.w, P.z));
            *(float4*)(orow + (size_t)r * D) = o;
        }
    }

    // bmix (row-tile 0 only): bmix[b,:] = bp0*sum(bv0) + bp1*sum(bv1)
    if (blockIdx.x == 0) {
        float bp0 = bp[2 * b], bp1 = bp[2 * b + 1];
        float4 b0 = make_float4(0.f, 0.f, 0.f, 0.f);
        float4 b1 = make_float4(0.f, 0.f, 0.f, 0.f);
#pragma unroll
        for (int ks = 0; ks < NKS; ks++) {
            const float* base = g_bv + (size_t)ks * NPAIR * D;
            float4 a = ((const float4*)(base + (size_t)(2 * b) * D))[t];
            float4 c = ((const float4*)(base + (size_t)(2 * b + 1) * D))[t];
            b0.x += a.x; b0.y += a.y; b0.z += a.z; b0.w += a.w;
            b1.x += c.x; b1.y += c.y; b1.z += c.z; b1.w += c.w;
        }
        float4 o;
        o.x = bp0 * b0.x + bp1 * b1.x;
        o.y = bp0 * b0.y + bp1 * b1.y;
        o.z = bp0 * b0.z + bp1 * b1.z;
        o.w = bp0 * b0.w + bp1 * b1.w;
        ((float4*)(outp + (size_t)BATCH * D * D + (size_t)b * D))[t] = o;
    }
}

// ---------------- launch ----------------
extern "C" void kernel_launch(void* const* d_in, const int* in_sizes, int n_in,
                              void* d_out, int out_size) {
    const float* x    = (const float*)d_in[0];
    const float* wp   = (const float*)d_in[1];
    const float* bpr  = (const float*)d_in[2];
    const float* iw   = (const float*)d_in[3];
    const float* ow   = (const float*)d_in[4];
    const float* dw   = (const float*)d_in[5];
    const float* bb   = (const float*)d_in[6];
    const int*   widx = (const int*)d_in[7];
    const int*   bidx = (const int*)d_in[8];
    float* outp = (float*)d_out;

    sort_kernel<<<1, NPAIR>>>(widx, bidx);
    gemm_kernel<<<dim3(4, MAXCH, 4 * NKS), 128>>>(x, iw, ow, dw, bb);
    mix_ln_kernel<<<dim3(4, BATCH), 128>>>(wp, bpr, outp);
}